// round 1
// baseline (speedup 1.0000x reference)
#include <cuda_runtime.h>
#include <cuda_bf16.h>

// Problem constants
#define B 64
#define H 256
#define S 4096
#define WCOLS 768   // W is (H, 3H) row-major

// GEMM tiling
#define BM 256      // h tile (all of H)
#define BN 64       // s tile
#define BK 16
#define TM 8
#define TN 8
#define THREADS 256

// Scratch (allocation-free rule: device globals)
__device__ float g_scores[B * S];
__device__ float g_bias[B * H];

// ---------------------------------------------------------------------------
// Kernel 0: bias[b,h] = sum_k W3[h,k] * decoder_hidden[b,k]
//           W3[h,k] = W[h*768 + 512 + k]
// ---------------------------------------------------------------------------
__global__ void bias_kernel(const float* __restrict__ W,
                            const float* __restrict__ dh,
                            float* __restrict__ bias) {
    int b = blockIdx.x;
    int h = threadIdx.x;
    __shared__ float sh[H];
    sh[h] = dh[b * H + h];
    __syncthreads();

    const float* Wr = W + h * WCOLS + 2 * H;
    float acc = 0.0f;
#pragma unroll 8
    for (int k = 0; k < H; k++) {
        acc = fmaf(Wr[k], sh[k], acc);
    }
    bias[b * H + h] = acc;
}

// ---------------------------------------------------------------------------
// Kernel 1: for each (b, s-tile): E[h,s] = sum_{k<512} Wc[h,k] * X[b,k,s]
//   Wc = W[:, :512] (= [W1 | W2] contiguous), X = [static_enc ; dynamic_enc]
//   then scores[b,s] = sum_h v[h] * tanh(E[h,s] + bias[b,h])
// Block tile: 256(h) x 64(s). 256 threads, 8x8 per-thread tile.
// ---------------------------------------------------------------------------
__global__ __launch_bounds__(THREADS, 2)
void energy_scores_kernel(const float* __restrict__ SE,
                          const float* __restrict__ DE,
                          const float* __restrict__ W,
                          const float* __restrict__ v,
                          const float* __restrict__ bias,
                          float* __restrict__ scores) {
    const int b  = blockIdx.y;
    const int s0 = blockIdx.x * BN;

    __shared__ float As[BK][BM + 1];  // +1 pad: conflict-free stores/loads
    __shared__ float Bs[BK][BN];

    const int tid = threadIdx.x;
    const int tx  = tid & 31;   // h-dimension lane (warp = fixed ty)
    const int ty  = tid >> 5;   // s-dimension

    float acc[TM][TN];
#pragma unroll
    for (int m = 0; m < TM; m++)
#pragma unroll
        for (int n = 0; n < TN; n++) acc[m][n] = 0.0f;

    const float* seb = SE + (size_t)b * H * S;
    const float* deb = DE + (size_t)b * H * S;

    const int w_kk  = tid & 15;   // k within tile for W loads
    const int w_hb  = tid >> 4;   // h sub-row
    const int x_row = tid >> 4;   // k row for X loads
    const int x_c4  = tid & 15;   // float4 column for X loads

    for (int k0 = 0; k0 < 2 * H; k0 += BK) {
        // W tile: As[kk][h] = W[h*768 + k0 + kk]   (Wc is contiguous cols 0..511)
#pragma unroll
        for (int i = 0; i < 16; i++) {
            int h = i * 16 + w_hb;
            As[w_kk][h] = W[h * WCOLS + k0 + w_kk];
        }
        // X tile: Bs[kk][sn], contiguous in s -> float4 coalesced
        const float* X = (k0 < H) ? (seb + (size_t)k0 * S)
                                  : (deb + (size_t)(k0 - H) * S);
        float4 xv = *(const float4*)(X + (size_t)x_row * S + s0 + x_c4 * 4);
        *(float4*)&Bs[x_row][x_c4 * 4] = xv;

        __syncthreads();

#pragma unroll
        for (int kk = 0; kk < BK; kk++) {
            float a[TM], bb[TN];
#pragma unroll
            for (int m = 0; m < TM; m++) a[m] = As[kk][tx * TM + m];
#pragma unroll
            for (int n = 0; n < TN; n++) bb[n] = Bs[kk][ty * TN + n];
#pragma unroll
            for (int m = 0; m < TM; m++)
#pragma unroll
                for (int n = 0; n < TN; n++)
                    acc[m][n] = fmaf(a[m], bb[n], acc[m][n]);
        }
        __syncthreads();
    }

    // Epilogue: part[n] = sum over this thread's 8 h of v[h]*tanh(acc + bias)
    float part[TN];
#pragma unroll
    for (int n = 0; n < TN; n++) part[n] = 0.0f;

#pragma unroll
    for (int m = 0; m < TM; m++) {
        int h = tx * TM + m;
        float bi = bias[b * H + h];
        float vh = v[h];
#pragma unroll
        for (int n = 0; n < TN; n++) {
            part[n] = fmaf(vh, tanhf(acc[m][n] + bi), part[n]);
        }
    }

    // Warp reduction over tx (all 32 lanes of a warp share ty -> same s columns)
#pragma unroll
    for (int off = 16; off; off >>= 1) {
#pragma unroll
        for (int n = 0; n < TN; n++)
            part[n] += __shfl_xor_sync(0xffffffffu, part[n], off);
    }

    if (tx == 0) {
#pragma unroll
        for (int n = 0; n < TN; n++)
            scores[(size_t)b * S + s0 + ty * TN + n] = part[n];
    }
}

// ---------------------------------------------------------------------------
// Kernel 2: row softmax over S=4096, one block per batch row.
// 256 threads x 16 values each.
// ---------------------------------------------------------------------------
__global__ void softmax_kernel(const float* __restrict__ scores,
                               float* __restrict__ out) {
    const int b   = blockIdx.x;
    const int tid = threadIdx.x;
    const float* row = scores + (size_t)b * S;

    float vals[16];
    float mx = -1e30f;
#pragma unroll
    for (int i = 0; i < 16; i++) {
        vals[i] = row[tid + i * 256];
        mx = fmaxf(mx, vals[i]);
    }
#pragma unroll
    for (int off = 16; off; off >>= 1)
        mx = fmaxf(mx, __shfl_xor_sync(0xffffffffu, mx, off));

    __shared__ float smax[8];
    __shared__ float ssum[8];
    if ((tid & 31) == 0) smax[tid >> 5] = mx;
    __syncthreads();
    float bm = smax[0];
#pragma unroll
    for (int w = 1; w < 8; w++) bm = fmaxf(bm, smax[w]);

    float sum = 0.0f;
#pragma unroll
    for (int i = 0; i < 16; i++) {
        vals[i] = __expf(vals[i] - bm);
        sum += vals[i];
    }
#pragma unroll
    for (int off = 16; off; off >>= 1)
        sum += __shfl_xor_sync(0xffffffffu, sum, off);
    if ((tid & 31) == 0) ssum[tid >> 5] = sum;
    __syncthreads();
    float tot = 0.0f;
#pragma unroll
    for (int w = 0; w < 8; w++) tot += ssum[w];
    float inv = 1.0f / tot;

#pragma unroll
    for (int i = 0; i < 16; i++)
        out[(size_t)b * S + tid + i * 256] = vals[i] * inv;
}

// ---------------------------------------------------------------------------
extern "C" void kernel_launch(void* const* d_in, const int* in_sizes, int n_in,
                              void* d_out, int out_size) {
    const float* static_enc  = (const float*)d_in[0];  // (B, H, S)
    const float* dynamic_enc = (const float*)d_in[1];  // (B, H, S)
    const float* dec_hidden  = (const float*)d_in[2];  // (B, H)
    const float* v           = (const float*)d_in[3];  // (1, H)
    const float* W           = (const float*)d_in[4];  // (H, 3H)
    float* out = (float*)d_out;                        // (B, S)

    float* bias_ptr;
    float* scores_ptr;
    cudaGetSymbolAddress((void**)&bias_ptr, g_bias);
    cudaGetSymbolAddress((void**)&scores_ptr, g_scores);

    bias_kernel<<<B, H>>>(W, dec_hidden, bias_ptr);

    dim3 grid(S / BN, B);
    energy_scores_kernel<<<grid, THREADS>>>(static_enc, dynamic_enc, W, v,
                                            bias_ptr, scores_ptr);

    softmax_kernel<<<B, 256>>>(scores_ptr, out);
}

// round 2
// speedup vs baseline: 1.6195x; 1.6195x over previous
#include <cuda_runtime.h>
#include <cuda_bf16.h>

// Problem constants
#define B 64
#define H 256
#define S 4096
#define WCOLS 768   // W is (H, 3H) row-major

// GEMM tiling
#define BM 256      // h tile (all of H)
#define BN 64       // s tile
#define BK 16
#define TM 8
#define TN 8
#define THREADS 256

// Scratch (allocation-free rule: device globals)
__device__ float g_scores[B * S];
__device__ float g_bias[B * H];

// ---------------------------------------------------------------------------
// Kernel 0: bias[b,h] = sum_k W3[h,k] * decoder_hidden[b,k]
//           W3[h,k] = W[h*768 + 512 + k]
// ---------------------------------------------------------------------------
__global__ void bias_kernel(const float* __restrict__ W,
                            const float* __restrict__ dh,
                            float* __restrict__ bias) {
    int b = blockIdx.x;
    int h = threadIdx.x;
    __shared__ float sh[H];
    sh[h] = dh[b * H + h];
    __syncthreads();

    const float* Wr = W + h * WCOLS + 2 * H;
    float acc = 0.0f;
#pragma unroll 8
    for (int k = 0; k < H; k++) {
        acc = fmaf(Wr[k], sh[k], acc);
    }
    bias[b * H + h] = acc;
}

// ---------------------------------------------------------------------------
// Kernel 1: for each (b, s-tile): E[h,s] = sum_{k<512} Wc[h,k] * X[b,k,s]
//   Wc = W[:, :512] (= [W1 | W2] contiguous), X = [static_enc ; dynamic_enc]
//   then scores[b,s] = sum_h v[h] * tanh(E[h,s] + bias[b,h])
// Block tile: 256(h) x 64(s). 256 threads, 8x8 per-thread tile.
// ---------------------------------------------------------------------------
__global__ __launch_bounds__(THREADS, 2)
void energy_scores_kernel(const float* __restrict__ SE,
                          const float* __restrict__ DE,
                          const float* __restrict__ W,
                          const float* __restrict__ v,
                          const float* __restrict__ bias,
                          float* __restrict__ scores) {
    const int b  = blockIdx.y;
    const int s0 = blockIdx.x * BN;

    __shared__ float As[BK][BM + 1];  // +1 pad: conflict-free stores/loads
    __shared__ float Bs[BK][BN];

    const int tid = threadIdx.x;
    const int tx  = tid & 31;   // h-dimension lane (warp = fixed ty)
    const int ty  = tid >> 5;   // s-dimension

    float acc[TM][TN];
#pragma unroll
    for (int m = 0; m < TM; m++)
#pragma unroll
        for (int n = 0; n < TN; n++) acc[m][n] = 0.0f;

    const float* seb = SE + (size_t)b * H * S;
    const float* deb = DE + (size_t)b * H * S;

    const int w_kk  = tid & 15;   // k within tile for W loads
    const int w_hb  = tid >> 4;   // h sub-row
    const int x_row = tid >> 4;   // k row for X loads
    const int x_c4  = tid & 15;   // float4 column for X loads

    for (int k0 = 0; k0 < 2 * H; k0 += BK) {
        // W tile: As[kk][h] = W[h*768 + k0 + kk]   (Wc is contiguous cols 0..511)
#pragma unroll
        for (int i = 0; i < 16; i++) {
            int h = i * 16 + w_hb;
            As[w_kk][h] = W[h * WCOLS + k0 + w_kk];
        }
        // X tile: Bs[kk][sn], contiguous in s -> float4 coalesced
        const float* X = (k0 < H) ? (seb + (size_t)k0 * S)
                                  : (deb + (size_t)(k0 - H) * S);
        float4 xv = *(const float4*)(X + (size_t)x_row * S + s0 + x_c4 * 4);
        *(float4*)&Bs[x_row][x_c4 * 4] = xv;

        __syncthreads();

#pragma unroll
        for (int kk = 0; kk < BK; kk++) {
            float a[TM], bb[TN];
#pragma unroll
            for (int m = 0; m < TM; m++) a[m] = As[kk][tx * TM + m];
#pragma unroll
            for (int n = 0; n < TN; n++) bb[n] = Bs[kk][ty * TN + n];
#pragma unroll
            for (int m = 0; m < TM; m++)
#pragma unroll
                for (int n = 0; n < TN; n++)
                    acc[m][n] = fmaf(a[m], bb[n], acc[m][n]);
        }
        __syncthreads();
    }

    // Epilogue: part[n] = sum over this thread's 8 h of v[h]*tanh(acc + bias)
    float part[TN];
#pragma unroll
    for (int n = 0; n < TN; n++) part[n] = 0.0f;

#pragma unroll
    for (int m = 0; m < TM; m++) {
        int h = tx * TM + m;
        float bi = bias[b * H + h];
        float vh = v[h];
#pragma unroll
        for (int n = 0; n < TN; n++) {
            part[n] = fmaf(vh, tanhf(acc[m][n] + bi), part[n]);
        }
    }

    // Warp reduction over tx (all 32 lanes of a warp share ty -> same s columns)
#pragma unroll
    for (int off = 16; off; off >>= 1) {
#pragma unroll
        for (int n = 0; n < TN; n++)
            part[n] += __shfl_xor_sync(0xffffffffu, part[n], off);
    }

    if (tx == 0) {
#pragma unroll
        for (int n = 0; n < TN; n++)
            scores[(size_t)b * S + s0 + ty * TN + n] = part[n];
    }
}

// ---------------------------------------------------------------------------
// Kernel 2: row softmax over S=4096, one block per batch row.
// 256 threads x 16 values each.
// ---------------------------------------------------------------------------
__global__ void softmax_kernel(const float* __restrict__ scores,
                               float* __restrict__ out) {
    const int b   = blockIdx.x;
    const int tid = threadIdx.x;
    const float* row = scores + (size_t)b * S;

    float vals[16];
    float mx = -1e30f;
#pragma unroll
    for (int i = 0; i < 16; i++) {
        vals[i] = row[tid + i * 256];
        mx = fmaxf(mx, vals[i]);
    }
#pragma unroll
    for (int off = 16; off; off >>= 1)
        mx = fmaxf(mx, __shfl_xor_sync(0xffffffffu, mx, off));

    __shared__ float smax[8];
    __shared__ float ssum[8];
    if ((tid & 31) == 0) smax[tid >> 5] = mx;
    __syncthreads();
    float bm = smax[0];
#pragma unroll
    for (int w = 1; w < 8; w++) bm = fmaxf(bm, smax[w]);

    float sum = 0.0f;
#pragma unroll
    for (int i = 0; i < 16; i++) {
        vals[i] = __expf(vals[i] - bm);
        sum += vals[i];
    }
#pragma unroll
    for (int off = 16; off; off >>= 1)
        sum += __shfl_xor_sync(0xffffffffu, sum, off);
    if ((tid & 31) == 0) ssum[tid >> 5] = sum;
    __syncthreads();
    float tot = 0.0f;
#pragma unroll
    for (int w = 0; w < 8; w++) tot += ssum[w];
    float inv = 1.0f / tot;

#pragma unroll
    for (int i = 0; i < 16; i++)
        out[(size_t)b * S + tid + i * 256] = vals[i] * inv;
}

// ---------------------------------------------------------------------------
extern "C" void kernel_launch(void* const* d_in, const int* in_sizes, int n_in,
                              void* d_out, int out_size) {
    const float* static_enc  = (const float*)d_in[0];  // (B, H, S)
    const float* dynamic_enc = (const float*)d_in[1];  // (B, H, S)
    const float* dec_hidden  = (const float*)d_in[2];  // (B, H)
    const float* v           = (const float*)d_in[3];  // (1, H)
    const float* W           = (const float*)d_in[4];  // (H, 3H)
    float* out = (float*)d_out;                        // (B, S)

    float* bias_ptr;
    float* scores_ptr;
    cudaGetSymbolAddress((void**)&bias_ptr, g_bias);
    cudaGetSymbolAddress((void**)&scores_ptr, g_scores);

    bias_kernel<<<B, H>>>(W, dec_hidden, bias_ptr);

    dim3 grid(S / BN, B);
    energy_scores_kernel<<<grid, THREADS>>>(static_enc, dynamic_enc, W, v,
                                            bias_ptr, scores_ptr);

    softmax_kernel<<<B, 256>>>(scores_ptr, out);
}

// round 4
// speedup vs baseline: 3.1214x; 1.9274x over previous
#include <cuda_runtime.h>
#include <cuda_bf16.h>
#include <cstdint>

#define Bn 64
#define Hn 256
#define Sn 4096

__device__ __nv_bfloat16 g_Wh[Hn * 512];
__device__ __nv_bfloat16 g_Wl[Hn * 512];
__device__ float g_scores[Bn * Sn];
__device__ float g_bias[Bn * Hn];

// ---- smem geometry (bytes) ----
#define W_STRIDE 80        // 32 bf16 (64B) + 16B pad -> conflict-free ldmatrix
#define X_STRIDE 144       // 64 bf16 (128B) + 16B pad
#define OFF_WH 0
#define OFF_WL 20480       // 256*80
#define OFF_XH 40960
#define OFF_XL 45568       // 40960 + 32*144
#define STAGE  50176       // 45568 + 32*144
#define SMEM_SZ (2 * STAGE)

// ---------------- PTX helpers (baseline ISA only — NO tcgen05) ----------------
__device__ __forceinline__ uint32_t smem_u32(const void* p) {
    uint32_t a;
    asm("{ .reg .u64 t; cvta.to.shared.u64 t, %1; cvt.u32.u64 %0, t; }" : "=r"(a) : "l"(p));
    return a;
}
__device__ __forceinline__ void ldsm_x4(uint32_t* r, uint32_t addr) {
    asm volatile("ldmatrix.sync.aligned.m8n8.x4.shared.b16 {%0,%1,%2,%3}, [%4];"
                 : "=r"(r[0]), "=r"(r[1]), "=r"(r[2]), "=r"(r[3]) : "r"(addr));
}
__device__ __forceinline__ void ldsm_x4_t(uint32_t* r, uint32_t addr) {
    asm volatile("ldmatrix.sync.aligned.m8n8.x4.trans.shared.b16 {%0,%1,%2,%3}, [%4];"
                 : "=r"(r[0]), "=r"(r[1]), "=r"(r[2]), "=r"(r[3]) : "r"(addr));
}
__device__ __forceinline__ void mma_bf16(float (&d)[4], const uint32_t (&a)[4],
                                         const uint32_t (&b)[2]) {
    asm volatile(
        "mma.sync.aligned.m16n8k16.row.col.f32.bf16.bf16.f32 "
        "{%0,%1,%2,%3}, {%4,%5,%6,%7}, {%8,%9}, {%0,%1,%2,%3};"
        : "+f"(d[0]), "+f"(d[1]), "+f"(d[2]), "+f"(d[3])
        : "r"(a[0]), "r"(a[1]), "r"(a[2]), "r"(a[3]), "r"(b[0]), "r"(b[1]));
}
#define CP_ASYNC16(s, g) \
    asm volatile("cp.async.cg.shared.global [%0], [%1], 16;" :: "r"(s), "l"(g))
#define CP_COMMIT() asm volatile("cp.async.commit_group;" ::: "memory")
#define CP_WAIT0()  asm volatile("cp.async.wait_group 0;" ::: "memory")

__device__ __forceinline__ float tanh_acc(float x) {
    float z = x * 2.885390082f;           // 2*log2(e)*x
    float e; asm("ex2.approx.f32 %0, %1;" : "=f"(e) : "f"(z));
    float r; asm("rcp.approx.f32 %0, %1;" : "=f"(r) : "f"(e + 1.0f));
    return fmaf(-2.0f, r, 1.0f);          // 1 - 2/(e^{2x}+1)
}

// convert 8 floats -> 8 bf16 hi + 8 bf16 lo
__device__ __forceinline__ void cvt8(float4 a, float4 b, uint4& hi, uint4& lo) {
    __nv_bfloat162 p0 = __floats2bfloat162_rn(a.x, a.y);
    __nv_bfloat162 p1 = __floats2bfloat162_rn(a.z, a.w);
    __nv_bfloat162 p2 = __floats2bfloat162_rn(b.x, b.y);
    __nv_bfloat162 p3 = __floats2bfloat162_rn(b.z, b.w);
    float2 f0 = __bfloat1622float2(p0), f1 = __bfloat1622float2(p1);
    float2 f2 = __bfloat1622float2(p2), f3 = __bfloat1622float2(p3);
    __nv_bfloat162 q0 = __floats2bfloat162_rn(a.x - f0.x, a.y - f0.y);
    __nv_bfloat162 q1 = __floats2bfloat162_rn(a.z - f1.x, a.w - f1.y);
    __nv_bfloat162 q2 = __floats2bfloat162_rn(b.x - f2.x, b.y - f2.y);
    __nv_bfloat162 q3 = __floats2bfloat162_rn(b.z - f3.x, b.w - f3.y);
    hi = make_uint4(*(uint32_t*)&p0, *(uint32_t*)&p1, *(uint32_t*)&p2, *(uint32_t*)&p3);
    lo = make_uint4(*(uint32_t*)&q0, *(uint32_t*)&q1, *(uint32_t*)&q2, *(uint32_t*)&q3);
}

// ---------------------------------------------------------------------------
__global__ void convert_w_kernel(const float* __restrict__ W,
                                 __nv_bfloat16* __restrict__ wh,
                                 __nv_bfloat16* __restrict__ wl) {
    int idx = blockIdx.x * 256 + threadIdx.x;  // 0..32767 float4 units
    int h = idx >> 7, c4 = idx & 127;
    float4 w = *(const float4*)(W + (size_t)h * 768 + c4 * 4);
    uint4 hi, lo;
    cvt8(w, make_float4(0.f, 0.f, 0.f, 0.f), hi, lo);
    // cvt8 packs 8 values; we only want first 4 -> redo manually for clarity
    __nv_bfloat162 h01 = __floats2bfloat162_rn(w.x, w.y);
    __nv_bfloat162 h23 = __floats2bfloat162_rn(w.z, w.w);
    float2 f01 = __bfloat1622float2(h01);
    float2 f23 = __bfloat1622float2(h23);
    __nv_bfloat162 l01 = __floats2bfloat162_rn(w.x - f01.x, w.y - f01.y);
    __nv_bfloat162 l23 = __floats2bfloat162_rn(w.z - f23.x, w.w - f23.y);
    uint2 hh = make_uint2(*(uint32_t*)&h01, *(uint32_t*)&h23);
    uint2 ll = make_uint2(*(uint32_t*)&l01, *(uint32_t*)&l23);
    *(uint2*)(wh + (size_t)h * 512 + c4 * 4) = hh;
    *(uint2*)(wl + (size_t)h * 512 + c4 * 4) = ll;
}

// bias[b,h] = W3[h,:] . dh[b,:]  — 1024 threads, 4 threads per h
__global__ void bias_kernel(const float* __restrict__ W,
                            const float* __restrict__ dh,
                            float* __restrict__ bias) {
    int b = blockIdx.x;
    int tid = threadIdx.x;
    __shared__ float sh[Hn];
    if (tid < Hn) sh[tid] = dh[b * Hn + tid];
    __syncthreads();
    int h = tid >> 2, q = tid & 3;
    const float4* Wr = (const float4*)(W + (size_t)h * 768 + 512 + q * 64);
    const float4* sr = (const float4*)(sh + q * 64);
    float a0 = 0.f, a1 = 0.f, a2 = 0.f, a3 = 0.f;
#pragma unroll
    for (int j = 0; j < 16; j++) {
        float4 w4 = __ldg(&Wr[j]); float4 s4 = sr[j];
        a0 = fmaf(w4.x, s4.x, a0); a1 = fmaf(w4.y, s4.y, a1);
        a2 = fmaf(w4.z, s4.z, a2); a3 = fmaf(w4.w, s4.w, a3);
    }
    float r = (a0 + a1) + (a2 + a3);
    r += __shfl_xor_sync(0xffffffffu, r, 1);
    r += __shfl_xor_sync(0xffffffffu, r, 2);
    if (q == 0) bias[b * Hn + h] = r;
}

// ---------------------------------------------------------------------------
// Main: grid (64 s-tiles, 64 b), 256 threads (8 warps: 4M x 2N).
// BM=256, BN=64, BK=32, 16 K-iters, 3-term bf16 split on classic mma.sync.
// ---------------------------------------------------------------------------
__global__ __launch_bounds__(256, 1)
void attn_main(const float* __restrict__ SE, const float* __restrict__ DE,
               const __nv_bfloat16* __restrict__ Wh, const __nv_bfloat16* __restrict__ Wl,
               const float* __restrict__ v, const float* __restrict__ bias,
               float* __restrict__ scores) {
    extern __shared__ __align__(128) char smem[];
    const uint32_t sb = smem_u32(smem);
    const int tid = threadIdx.x, wid = tid >> 5, lane = tid & 31;
    const int wm = wid & 3, wn = wid >> 2;
    const int b = blockIdx.y;
    const int s0 = blockIdx.x * 64;

    const float* seb = SE + (size_t)b * Hn * Sn;
    const float* deb = DE + (size_t)b * Hn * Sn;

    // X load mapping: 8 floats/thread: row kr, col chunk c8
    const int kr = tid >> 3;          // 0..31
    const int c8 = (tid & 7) * 8;     // 0..56

    float acc[4][4][4];
#pragma unroll
    for (int mt = 0; mt < 4; mt++)
#pragma unroll
        for (int nt = 0; nt < 4; nt++)
#pragma unroll
            for (int r = 0; r < 4; r++) acc[mt][nt][r] = 0.f;

    // ---- prologue: W stage0 via cp.async, X stage0 via regs ----
    {
        uint32_t s = sb + tid * W_STRIDE;
        const char* gh = (const char*)(Wh + (size_t)tid * 512);
        const char* gl = (const char*)(Wl + (size_t)tid * 512);
#pragma unroll
        for (int c = 0; c < 4; c++) {
            CP_ASYNC16(s + OFF_WH + c * 16, gh + c * 16);
            CP_ASYNC16(s + OFF_WL + c * 16, gl + c * 16);
        }
        CP_COMMIT();
        const float* base = seb + (size_t)kr * Sn + s0 + c8;
        float4 xa = *(const float4*)base;
        float4 xb = *(const float4*)(base + 4);
        uint4 hi, lo; cvt8(xa, xb, hi, lo);
        uint32_t xoff = (uint32_t)(kr * X_STRIDE + (tid & 7) * 16);
        *(uint4*)(smem + OFF_XH + xoff) = hi;
        *(uint4*)(smem + OFF_XL + xoff) = lo;
    }

    const uint32_t arow = (uint32_t)((lane & 15) * W_STRIDE + (lane >> 4) * 16);
    const uint32_t xrow = (uint32_t)((lane & 15) * X_STRIDE + (lane >> 4) * 16);

    float4 xa, xb;
    for (int kc = 0; kc < 16; kc++) {
        const int buf = kc & 1;
        CP_WAIT0();
        __syncthreads();

        if (kc < 15) {
            // prefetch W(kc+1) into buf^1
            uint32_t s = sb + (buf ^ 1) * STAGE + tid * W_STRIDE;
            const char* gh = (const char*)(Wh + (size_t)tid * 512 + (kc + 1) * 32);
            const char* gl = (const char*)(Wl + (size_t)tid * 512 + (kc + 1) * 32);
#pragma unroll
            for (int c = 0; c < 4; c++) {
                CP_ASYNC16(s + OFF_WH + c * 16, gh + c * 16);
                CP_ASYNC16(s + OFF_WL + c * 16, gl + c * 16);
            }
            CP_COMMIT();
            // load X(kc+1) into regs
            int kn = kc + 1;
            const float* base = ((kn < 8) ? seb : deb)
                              + (size_t)((kn & 7) * 32 + kr) * Sn + s0 + c8;
            xa = *(const float4*)base;
            xb = *(const float4*)(base + 4);
        }

        // ---- MMA on stage buf ----
        const uint32_t stage = sb + buf * STAGE;
#pragma unroll
        for (int ks = 0; ks < 2; ks++) {
            uint32_t aH[4][4], aL[4][4], bH[4][2], bL[4][2];
#pragma unroll
            for (int mt = 0; mt < 4; mt++) {
                uint32_t ad = stage + OFF_WH + (uint32_t)((wm * 64 + mt * 16) * W_STRIDE + ks * 32) + arow;
                ldsm_x4(aH[mt], ad);
                ldsm_x4(aL[mt], ad + (OFF_WL - OFF_WH));
            }
#pragma unroll
            for (int np = 0; np < 2; np++) {
                uint32_t bd = stage + OFF_XH + (uint32_t)(ks * 16 * X_STRIDE + (wn * 32 + np * 16) * 2) + xrow;
                uint32_t t[4];
                ldsm_x4_t(t, bd);
                bH[2 * np][0] = t[0]; bH[2 * np][1] = t[1];
                bH[2 * np + 1][0] = t[2]; bH[2 * np + 1][1] = t[3];
                ldsm_x4_t(t, bd + (OFF_XL - OFF_XH));
                bL[2 * np][0] = t[0]; bL[2 * np][1] = t[1];
                bL[2 * np + 1][0] = t[2]; bL[2 * np + 1][1] = t[3];
            }
#pragma unroll
            for (int mt = 0; mt < 4; mt++)
#pragma unroll
                for (int nt = 0; nt < 4; nt++) {
                    mma_bf16(acc[mt][nt], aH[mt], bH[nt]);
                    mma_bf16(acc[mt][nt], aL[mt], bH[nt]);
                    mma_bf16(acc[mt][nt], aH[mt], bL[nt]);
                }
        }

        if (kc < 15) {
            // store X(kc+1) into buf^1
            uint4 hi, lo; cvt8(xa, xb, hi, lo);
            uint32_t xoff = (uint32_t)((buf ^ 1) * STAGE + kr * X_STRIDE + (tid & 7) * 16);
            *(uint4*)(smem + OFF_XH + xoff) = hi;
            *(uint4*)(smem + OFF_XL + xoff) = lo;
        }
    }

    // ---- epilogue: p = v[h]*tanh(acc+bias[h]); reduce over h ----
    float colsum[4][2];
#pragma unroll
    for (int nt = 0; nt < 4; nt++) { colsum[nt][0] = 0.f; colsum[nt][1] = 0.f; }

#pragma unroll
    for (int mt = 0; mt < 4; mt++) {
        int h0 = wm * 64 + mt * 16 + (lane >> 2);
        float bi0 = bias[b * Hn + h0],     v0 = v[h0];
        float bi1 = bias[b * Hn + h0 + 8], v1 = v[h0 + 8];
#pragma unroll
        for (int nt = 0; nt < 4; nt++) {
            colsum[nt][0] += v0 * tanh_acc(acc[mt][nt][0] + bi0)
                           + v1 * tanh_acc(acc[mt][nt][2] + bi1);
            colsum[nt][1] += v0 * tanh_acc(acc[mt][nt][1] + bi0)
                           + v1 * tanh_acc(acc[mt][nt][3] + bi1);
        }
    }
#pragma unroll
    for (int off = 4; off < 32; off <<= 1)
#pragma unroll
        for (int nt = 0; nt < 4; nt++) {
            colsum[nt][0] += __shfl_xor_sync(0xffffffffu, colsum[nt][0], off);
            colsum[nt][1] += __shfl_xor_sync(0xffffffffu, colsum[nt][1], off);
        }

    __syncthreads();  // everyone done with smem stage data
    float* spart = (float*)smem;  // [4][64]
    if (lane < 4) {
#pragma unroll
        for (int nt = 0; nt < 4; nt++) {
            spart[wm * 64 + wn * 32 + nt * 8 + lane * 2 + 0] = colsum[nt][0];
            spart[wm * 64 + wn * 32 + nt * 8 + lane * 2 + 1] = colsum[nt][1];
        }
    }
    __syncthreads();
    if (tid < 64) {
        float sc = spart[tid] + spart[64 + tid] + spart[128 + tid] + spart[192 + tid];
        scores[(size_t)b * Sn + s0 + tid] = sc;
    }
}

// ---------------------------------------------------------------------------
__global__ void softmax_kernel(const float* __restrict__ scores,
                               float* __restrict__ out) {
    const int b = blockIdx.x, tid = threadIdx.x;
    const float* row = scores + (size_t)b * Sn;
    float vals[16];
    float mx = -1e30f;
#pragma unroll
    for (int i = 0; i < 16; i++) {
        vals[i] = row[tid + i * 256];
        mx = fmaxf(mx, vals[i]);
    }
#pragma unroll
    for (int off = 16; off; off >>= 1)
        mx = fmaxf(mx, __shfl_xor_sync(0xffffffffu, mx, off));
    __shared__ float sred[8];
    if ((tid & 31) == 0) sred[tid >> 5] = mx;
    __syncthreads();
    float bm = sred[0];
#pragma unroll
    for (int w = 1; w < 8; w++) bm = fmaxf(bm, sred[w]);
    __syncthreads();
    float sum = 0.f;
#pragma unroll
    for (int i = 0; i < 16; i++) { vals[i] = __expf(vals[i] - bm); sum += vals[i]; }
#pragma unroll
    for (int off = 16; off; off >>= 1)
        sum += __shfl_xor_sync(0xffffffffu, sum, off);
    if ((tid & 31) == 0) sred[tid >> 5] = sum;
    __syncthreads();
    float tot = 0.f;
#pragma unroll
    for (int w = 0; w < 8; w++) tot += sred[w];
    float inv = 1.0f / tot;
#pragma unroll
    for (int i = 0; i < 16; i++)
        out[(size_t)b * Sn + tid + i * 256] = vals[i] * inv;
}

// ---------------------------------------------------------------------------
extern "C" void kernel_launch(void* const* d_in, const int* in_sizes, int n_in,
                              void* d_out, int out_size) {
    const float* SE = (const float*)d_in[0];
    const float* DE = (const float*)d_in[1];
    const float* dh = (const float*)d_in[2];
    const float* v  = (const float*)d_in[3];
    const float* W  = (const float*)d_in[4];
    float* out = (float*)d_out;

    __nv_bfloat16 *wh, *wl; float *bias, *scores;
    cudaGetSymbolAddress((void**)&wh, g_Wh);
    cudaGetSymbolAddress((void**)&wl, g_Wl);
    cudaGetSymbolAddress((void**)&bias, g_bias);
    cudaGetSymbolAddress((void**)&scores, g_scores);

    cudaFuncSetAttribute(attn_main, cudaFuncAttributeMaxDynamicSharedMemorySize, SMEM_SZ);

    convert_w_kernel<<<128, 256>>>(W, wh, wl);
    bias_kernel<<<Bn, 1024>>>(W, dh, bias);
    attn_main<<<dim3(64, Bn), 256, SMEM_SZ>>>(SE, DE, wh, wl, v, bias, scores);
    softmax_kernel<<<Bn, 256>>>(scores, out);
}

// round 5
// speedup vs baseline: 4.3630x; 1.3978x over previous
#include <cuda_runtime.h>
#include <cuda_fp16.h>
#include <cstdint>

#define Bn 64
#define Hn 256
#define Sn 4096

__device__ __half g_Wh[Hn * 512];
__device__ __half g_Wl[Hn * 512];
__device__ float g_scores[Bn * Sn];
__device__ float g_bias[Bn * Hn];

// ---- smem geometry (bytes) ----
#define W_STRIDE 80        // 32 fp16 (64B) + 16B pad -> conflict-free ldmatrix
#define X_STRIDE 144       // 64 fp16 (128B) + 16B pad
#define OFF_WH 0
#define OFF_WL 20480       // 256*80
#define OFF_XH 40960
#define STAGE  45568       // 40960 + 32*144
#define SMEM_SZ (2 * STAGE)

// ---------------- PTX helpers (baseline ISA only) ----------------
__device__ __forceinline__ uint32_t smem_u32(const void* p) {
    uint32_t a;
    asm("{ .reg .u64 t; cvta.to.shared.u64 t, %1; cvt.u32.u64 %0, t; }" : "=r"(a) : "l"(p));
    return a;
}
__device__ __forceinline__ void ldsm_x4(uint32_t* r, uint32_t addr) {
    asm volatile("ldmatrix.sync.aligned.m8n8.x4.shared.b16 {%0,%1,%2,%3}, [%4];"
                 : "=r"(r[0]), "=r"(r[1]), "=r"(r[2]), "=r"(r[3]) : "r"(addr));
}
__device__ __forceinline__ void ldsm_x4_t(uint32_t* r, uint32_t addr) {
    asm volatile("ldmatrix.sync.aligned.m8n8.x4.trans.shared.b16 {%0,%1,%2,%3}, [%4];"
                 : "=r"(r[0]), "=r"(r[1]), "=r"(r[2]), "=r"(r[3]) : "r"(addr));
}
__device__ __forceinline__ void mma_f16(float (&d)[4], const uint32_t (&a)[4],
                                        const uint32_t (&b)[2]) {
    asm volatile(
        "mma.sync.aligned.m16n8k16.row.col.f32.f16.f16.f32 "
        "{%0,%1,%2,%3}, {%4,%5,%6,%7}, {%8,%9}, {%0,%1,%2,%3};"
        : "+f"(d[0]), "+f"(d[1]), "+f"(d[2]), "+f"(d[3])
        : "r"(a[0]), "r"(a[1]), "r"(a[2]), "r"(a[3]), "r"(b[0]), "r"(b[1]));
}
#define CP_ASYNC16(s, g) \
    asm volatile("cp.async.cg.shared.global [%0], [%1], 16;" :: "r"(s), "l"(g))
#define CP_COMMIT() asm volatile("cp.async.commit_group;" ::: "memory")
#define CP_WAIT0()  asm volatile("cp.async.wait_group 0;" ::: "memory")

__device__ __forceinline__ float tanh_acc(float x) {
    float z = x * 2.885390082f;           // 2*log2(e)*x
    float e; asm("ex2.approx.f32 %0, %1;" : "=f"(e) : "f"(z));
    float r; asm("rcp.approx.f32 %0, %1;" : "=f"(r) : "f"(e + 1.0f));
    return fmaf(-2.0f, r, 1.0f);          // 1 - 2/(e^{2x}+1)
}

// 8 floats -> 8 fp16 (one uint4)
__device__ __forceinline__ uint4 cvt8h(float4 a, float4 b) {
    __half2 p0 = __floats2half2_rn(a.x, a.y);
    __half2 p1 = __floats2half2_rn(a.z, a.w);
    __half2 p2 = __floats2half2_rn(b.x, b.y);
    __half2 p3 = __floats2half2_rn(b.z, b.w);
    return make_uint4(*(uint32_t*)&p0, *(uint32_t*)&p1,
                      *(uint32_t*)&p2, *(uint32_t*)&p3);
}

// ---------------------------------------------------------------------------
__global__ void convert_w_kernel(const float* __restrict__ W,
                                 __half* __restrict__ wh,
                                 __half* __restrict__ wl) {
    int idx = blockIdx.x * 256 + threadIdx.x;  // 0..32767 float4 units
    int h = idx >> 7, c4 = idx & 127;
    float4 w = *(const float4*)(W + (size_t)h * 768 + c4 * 4);
    __half2 h01 = __floats2half2_rn(w.x, w.y);
    __half2 h23 = __floats2half2_rn(w.z, w.w);
    float2 f01 = __half22float2(h01);
    float2 f23 = __half22float2(h23);
    __half2 l01 = __floats2half2_rn(w.x - f01.x, w.y - f01.y);
    __half2 l23 = __floats2half2_rn(w.z - f23.x, w.w - f23.y);
    uint2 hh = make_uint2(*(uint32_t*)&h01, *(uint32_t*)&h23);
    uint2 ll = make_uint2(*(uint32_t*)&l01, *(uint32_t*)&l23);
    *(uint2*)(wh + (size_t)h * 512 + c4 * 4) = hh;
    *(uint2*)(wl + (size_t)h * 512 + c4 * 4) = ll;
}

// bias[b,h] = W3[h,:] . dh[b,:]
__global__ void bias_kernel(const float* __restrict__ W,
                            const float* __restrict__ dh,
                            float* __restrict__ bias) {
    int b = blockIdx.x;
    int tid = threadIdx.x;
    __shared__ float sh[Hn];
    if (tid < Hn) sh[tid] = dh[b * Hn + tid];
    __syncthreads();
    int h = tid >> 2, q = tid & 3;
    const float4* Wr = (const float4*)(W + (size_t)h * 768 + 512 + q * 64);
    const float4* sr = (const float4*)(sh + q * 64);
    float a0 = 0.f, a1 = 0.f, a2 = 0.f, a3 = 0.f;
#pragma unroll
    for (int j = 0; j < 16; j++) {
        float4 w4 = __ldg(&Wr[j]); float4 s4 = sr[j];
        a0 = fmaf(w4.x, s4.x, a0); a1 = fmaf(w4.y, s4.y, a1);
        a2 = fmaf(w4.z, s4.z, a2); a3 = fmaf(w4.w, s4.w, a3);
    }
    float r = (a0 + a1) + (a2 + a3);
    r += __shfl_xor_sync(0xffffffffu, r, 1);
    r += __shfl_xor_sync(0xffffffffu, r, 2);
    if (q == 0) bias[b * Hn + h] = r;
}

// ---------------------------------------------------------------------------
// Main: grid (64 s-tiles, 64 b), 256 threads (8 warps: 4M x 2N).
// BM=256, BN=64, BK=32, 16 K-iters. fp16 2-term split: Wh*Xh + Wl*Xh.
// ---------------------------------------------------------------------------
__global__ __launch_bounds__(256, 2)
void attn_main(const float* __restrict__ SE, const float* __restrict__ DE,
               const __half* __restrict__ Wh, const __half* __restrict__ Wl,
               const float* __restrict__ v, const float* __restrict__ bias,
               float* __restrict__ scores) {
    extern __shared__ __align__(128) char smem[];
    const uint32_t sb = smem_u32(smem);
    const int tid = threadIdx.x, wid = tid >> 5, lane = tid & 31;
    const int wm = wid & 3, wn = wid >> 2;
    const int b = blockIdx.y;
    const int s0 = blockIdx.x * 64;

    const float* seb = SE + (size_t)b * Hn * Sn;
    const float* deb = DE + (size_t)b * Hn * Sn;

    // X load mapping: 8 floats/thread: row kr, col chunk c8
    const int kr = tid >> 3;          // 0..31
    const int c8 = (tid & 7) * 8;     // 0..56

    float acc[4][4][4];
#pragma unroll
    for (int mt = 0; mt < 4; mt++)
#pragma unroll
        for (int nt = 0; nt < 4; nt++)
#pragma unroll
            for (int r = 0; r < 4; r++) acc[mt][nt][r] = 0.f;

    // ---- prologue: W stage0 via cp.async, X stage0 via regs ----
    {
        uint32_t s = sb + tid * W_STRIDE;
        const char* gh = (const char*)(Wh + (size_t)tid * 512);
        const char* gl = (const char*)(Wl + (size_t)tid * 512);
#pragma unroll
        for (int c = 0; c < 4; c++) {
            CP_ASYNC16(s + OFF_WH + c * 16, gh + c * 16);
            CP_ASYNC16(s + OFF_WL + c * 16, gl + c * 16);
        }
        CP_COMMIT();
        const float* base = seb + (size_t)kr * Sn + s0 + c8;
        float4 xa = *(const float4*)base;
        float4 xb = *(const float4*)(base + 4);
        uint32_t xoff = (uint32_t)(kr * X_STRIDE + (tid & 7) * 16);
        *(uint4*)(smem + OFF_XH + xoff) = cvt8h(xa, xb);
    }

    const uint32_t arow = (uint32_t)((lane & 15) * W_STRIDE + (lane >> 4) * 16);
    const uint32_t xrow = (uint32_t)((lane & 15) * X_STRIDE + (lane >> 4) * 16);

    float4 xa, xb;
    for (int kc = 0; kc < 16; kc++) {
        const int buf = kc & 1;
        CP_WAIT0();
        __syncthreads();

        if (kc < 15) {
            // prefetch W(kc+1) into buf^1
            uint32_t s = sb + (buf ^ 1) * STAGE + tid * W_STRIDE;
            const char* gh = (const char*)(Wh + (size_t)tid * 512 + (kc + 1) * 32);
            const char* gl = (const char*)(Wl + (size_t)tid * 512 + (kc + 1) * 32);
#pragma unroll
            for (int c = 0; c < 4; c++) {
                CP_ASYNC16(s + OFF_WH + c * 16, gh + c * 16);
                CP_ASYNC16(s + OFF_WL + c * 16, gl + c * 16);
            }
            CP_COMMIT();
            // load X(kc+1) into regs
            int kn = kc + 1;
            const float* base = ((kn < 8) ? seb : deb)
                              + (size_t)((kn & 7) * 32 + kr) * Sn + s0 + c8;
            xa = *(const float4*)base;
            xb = *(const float4*)(base + 4);
        }

        // ---- MMA on stage buf ----
        const uint32_t stage = sb + buf * STAGE;
#pragma unroll
        for (int ks = 0; ks < 2; ks++) {
            uint32_t aH[4][4], aL[4][4], bH[4][2];
#pragma unroll
            for (int mt = 0; mt < 4; mt++) {
                uint32_t ad = stage + OFF_WH
                    + (uint32_t)((wm * 64 + mt * 16) * W_STRIDE + ks * 32) + arow;
                ldsm_x4(aH[mt], ad);
                ldsm_x4(aL[mt], ad + (OFF_WL - OFF_WH));
            }
#pragma unroll
            for (int np = 0; np < 2; np++) {
                uint32_t bd = stage + OFF_XH
                    + (uint32_t)(ks * 16 * X_STRIDE + (wn * 32 + np * 16) * 2) + xrow;
                uint32_t t[4];
                ldsm_x4_t(t, bd);
                bH[2 * np][0] = t[0];     bH[2 * np][1] = t[1];
                bH[2 * np + 1][0] = t[2]; bH[2 * np + 1][1] = t[3];
            }
            // term-outermost: dependent MMAs to same acc are 16 apart
#pragma unroll
            for (int mt = 0; mt < 4; mt++)
#pragma unroll
                for (int nt = 0; nt < 4; nt++)
                    mma_f16(acc[mt][nt], aH[mt], bH[nt]);
#pragma unroll
            for (int mt = 0; mt < 4; mt++)
#pragma unroll
                for (int nt = 0; nt < 4; nt++)
                    mma_f16(acc[mt][nt], aL[mt], bH[nt]);
        }

        if (kc < 15) {
            uint32_t xoff = (uint32_t)((buf ^ 1) * STAGE + kr * X_STRIDE + (tid & 7) * 16);
            *(uint4*)(smem + OFF_XH + xoff) = cvt8h(xa, xb);
        }
    }

    // ---- epilogue: p = v[h]*tanh(acc+bias[h]); reduce over h ----
    float colsum[4][2];
#pragma unroll
    for (int nt = 0; nt < 4; nt++) { colsum[nt][0] = 0.f; colsum[nt][1] = 0.f; }

#pragma unroll
    for (int mt = 0; mt < 4; mt++) {
        int h0 = wm * 64 + mt * 16 + (lane >> 2);
        float bi0 = bias[b * Hn + h0],     v0 = v[h0];
        float bi1 = bias[b * Hn + h0 + 8], v1 = v[h0 + 8];
#pragma unroll
        for (int nt = 0; nt < 4; nt++) {
            colsum[nt][0] += v0 * tanh_acc(acc[mt][nt][0] + bi0)
                           + v1 * tanh_acc(acc[mt][nt][2] + bi1);
            colsum[nt][1] += v0 * tanh_acc(acc[mt][nt][1] + bi0)
                           + v1 * tanh_acc(acc[mt][nt][3] + bi1);
        }
    }
#pragma unroll
    for (int off = 4; off < 32; off <<= 1)
#pragma unroll
        for (int nt = 0; nt < 4; nt++) {
            colsum[nt][0] += __shfl_xor_sync(0xffffffffu, colsum[nt][0], off);
            colsum[nt][1] += __shfl_xor_sync(0xffffffffu, colsum[nt][1], off);
        }

    __syncthreads();  // stage data no longer needed
    float* spart = (float*)smem;  // [4][64]
    if (lane < 4) {
#pragma unroll
        for (int nt = 0; nt < 4; nt++) {
            spart[wm * 64 + wn * 32 + nt * 8 + lane * 2 + 0] = colsum[nt][0];
            spart[wm * 64 + wn * 32 + nt * 8 + lane * 2 + 1] = colsum[nt][1];
        }
    }
    __syncthreads();
    if (tid < 64) {
        float sc = spart[tid] + spart[64 + tid] + spart[128 + tid] + spart[192 + tid];
        scores[(size_t)b * Sn + s0 + tid] = sc;
    }
}

// ---------------------------------------------------------------------------
__global__ void softmax_kernel(const float* __restrict__ scores,
                               float* __restrict__ out) {
    const int b = blockIdx.x, tid = threadIdx.x;
    const float* row = scores + (size_t)b * Sn;
    float vals[16];
    float mx = -1e30f;
#pragma unroll
    for (int i = 0; i < 16; i++) {
        vals[i] = row[tid + i * 256];
        mx = fmaxf(mx, vals[i]);
    }
#pragma unroll
    for (int off = 16; off; off >>= 1)
        mx = fmaxf(mx, __shfl_xor_sync(0xffffffffu, mx, off));
    __shared__ float sred[8];
    if ((tid & 31) == 0) sred[tid >> 5] = mx;
    __syncthreads();
    float bm = sred[0];
#pragma unroll
    for (int w = 1; w < 8; w++) bm = fmaxf(bm, sred[w]);
    __syncthreads();
    float sum = 0.f;
#pragma unroll
    for (int i = 0; i < 16; i++) { vals[i] = __expf(vals[i] - bm); sum += vals[i]; }
#pragma unroll
    for (int off = 16; off; off >>= 1)
        sum += __shfl_xor_sync(0xffffffffu, sum, off);
    if ((tid & 31) == 0) sred[tid >> 5] = sum;
    __syncthreads();
    float tot = 0.f;
#pragma unroll
    for (int w = 0; w < 8; w++) tot += sred[w];
    float inv = 1.0f / tot;
#pragma unroll
    for (int i = 0; i < 16; i++)
        out[(size_t)b * Sn + tid + i * 256] = vals[i] * inv;
}

// ---------------------------------------------------------------------------
extern "C" void kernel_launch(void* const* d_in, const int* in_sizes, int n_in,
                              void* d_out, int out_size) {
    const float* SE = (const float*)d_in[0];
    const float* DE = (const float*)d_in[1];
    const float* dh = (const float*)d_in[2];
    const float* v  = (const float*)d_in[3];
    const float* W  = (const float*)d_in[4];
    float* out = (float*)d_out;

    __half *wh, *wl; float *bias, *scores;
    cudaGetSymbolAddress((void**)&wh, g_Wh);
    cudaGetSymbolAddress((void**)&wl, g_Wl);
    cudaGetSymbolAddress((void**)&bias, g_bias);
    cudaGetSymbolAddress((void**)&scores, g_scores);

    cudaFuncSetAttribute(attn_main, cudaFuncAttributeMaxDynamicSharedMemorySize, SMEM_SZ);

    convert_w_kernel<<<128, 256>>>(W, wh, wl);
    bias_kernel<<<Bn, 1024>>>(W, dh, bias);
    attn_main<<<dim3(64, Bn), 256, SMEM_SZ>>>(SE, DE, wh, wl, v, bias, scores);
    softmax_kernel<<<Bn, 256>>>(scores, out);
}

// round 6
// speedup vs baseline: 7.3893x; 1.6936x over previous
#include <cuda_runtime.h>
#include <cuda_fp16.h>
#include <cstdint>

#define Bn 64
#define Hn 256
#define Sn 4096

__device__ __half g_Wh[Hn * 512];
__device__ float g_scores[Bn * Sn];
__device__ float g_bias[Bn * Hn];

// ---- smem geometry (bytes) ----
#define W_STRIDE 80        // 32 fp16 (64B) + 16B pad -> conflict-free ldmatrix
#define X_STRIDE 144       // 64 fp16 (128B) + 16B pad
#define OFF_WH 0
#define OFF_XH 20480       // 256*80
#define STAGE  25088       // 20480 + 32*144
#define SMEM_SZ (2 * STAGE)

// ---------------- PTX helpers (baseline ISA only) ----------------
__device__ __forceinline__ uint32_t smem_u32(const void* p) {
    uint32_t a;
    asm("{ .reg .u64 t; cvta.to.shared.u64 t, %1; cvt.u32.u64 %0, t; }" : "=r"(a) : "l"(p));
    return a;
}
__device__ __forceinline__ void ldsm_x4(uint32_t* r, uint32_t addr) {
    asm volatile("ldmatrix.sync.aligned.m8n8.x4.shared.b16 {%0,%1,%2,%3}, [%4];"
                 : "=r"(r[0]), "=r"(r[1]), "=r"(r[2]), "=r"(r[3]) : "r"(addr));
}
__device__ __forceinline__ void ldsm_x4_t(uint32_t* r, uint32_t addr) {
    asm volatile("ldmatrix.sync.aligned.m8n8.x4.trans.shared.b16 {%0,%1,%2,%3}, [%4];"
                 : "=r"(r[0]), "=r"(r[1]), "=r"(r[2]), "=r"(r[3]) : "r"(addr));
}
__device__ __forceinline__ void mma_f16(float (&d)[4], const uint32_t (&a)[4],
                                        const uint32_t (&b)[2]) {
    asm volatile(
        "mma.sync.aligned.m16n8k16.row.col.f32.f16.f16.f32 "
        "{%0,%1,%2,%3}, {%4,%5,%6,%7}, {%8,%9}, {%0,%1,%2,%3};"
        : "+f"(d[0]), "+f"(d[1]), "+f"(d[2]), "+f"(d[3])
        : "r"(a[0]), "r"(a[1]), "r"(a[2]), "r"(a[3]), "r"(b[0]), "r"(b[1]));
}
#define CP_ASYNC16(s, g) \
    asm volatile("cp.async.cg.shared.global [%0], [%1], 16;" :: "r"(s), "l"(g))
#define CP_COMMIT() asm volatile("cp.async.commit_group;" ::: "memory")
#define CP_WAIT0()  asm volatile("cp.async.wait_group 0;" ::: "memory")

__device__ __forceinline__ float tanh_acc(float x) {
    float z = x * 2.885390082f;           // 2*log2(e)*x
    float e; asm("ex2.approx.f32 %0, %1;" : "=f"(e) : "f"(z));
    float r; asm("rcp.approx.f32 %0, %1;" : "=f"(r) : "f"(e + 1.0f));
    return fmaf(-2.0f, r, 1.0f);          // 1 - 2/(e^{2x}+1)
}

// 8 floats -> 8 fp16 (one uint4)
__device__ __forceinline__ uint4 cvt8h(float4 a, float4 b) {
    __half2 p0 = __floats2half2_rn(a.x, a.y);
    __half2 p1 = __floats2half2_rn(a.z, a.w);
    __half2 p2 = __floats2half2_rn(b.x, b.y);
    __half2 p3 = __floats2half2_rn(b.z, b.w);
    return make_uint4(*(uint32_t*)&p0, *(uint32_t*)&p1,
                      *(uint32_t*)&p2, *(uint32_t*)&p3);
}

// ---------------------------------------------------------------------------
__global__ void convert_w_kernel(const float* __restrict__ W,
                                 __half* __restrict__ wh) {
    int idx = blockIdx.x * 256 + threadIdx.x;  // 0..32767 float4 units
    int h = idx >> 7, c4 = idx & 127;
    float4 w = *(const float4*)(W + (size_t)h * 768 + c4 * 4);
    __half2 h01 = __floats2half2_rn(w.x, w.y);
    __half2 h23 = __floats2half2_rn(w.z, w.w);
    uint2 hh = make_uint2(*(uint32_t*)&h01, *(uint32_t*)&h23);
    *(uint2*)(wh + (size_t)h * 512 + c4 * 4) = hh;
}

// bias[b,h] = W3[h,:] . dh[b,:]  (fp32, exact path)
__global__ void bias_kernel(const float* __restrict__ W,
                            const float* __restrict__ dh,
                            float* __restrict__ bias) {
    int b = blockIdx.x;
    int tid = threadIdx.x;
    __shared__ float sh[Hn];
    if (tid < Hn) sh[tid] = dh[b * Hn + tid];
    __syncthreads();
    int h = tid >> 2, q = tid & 3;
    const float4* Wr = (const float4*)(W + (size_t)h * 768 + 512 + q * 64);
    const float4* sr = (const float4*)(sh + q * 64);
    float a0 = 0.f, a1 = 0.f, a2 = 0.f, a3 = 0.f;
#pragma unroll
    for (int j = 0; j < 16; j++) {
        float4 w4 = __ldg(&Wr[j]); float4 s4 = sr[j];
        a0 = fmaf(w4.x, s4.x, a0); a1 = fmaf(w4.y, s4.y, a1);
        a2 = fmaf(w4.z, s4.z, a2); a3 = fmaf(w4.w, s4.w, a3);
    }
    float r = (a0 + a1) + (a2 + a3);
    r += __shfl_xor_sync(0xffffffffu, r, 1);
    r += __shfl_xor_sync(0xffffffffu, r, 2);
    if (q == 0) bias[b * Hn + h] = r;
}

// ---------------------------------------------------------------------------
// Main: grid (64 s-tiles, 64 b), 256 threads (8 warps: 4M x 2N).
// BM=256, BN=64, BK=32, 16 K-iters. Single-term fp16: Wh*Xh.
// ---------------------------------------------------------------------------
__global__ __launch_bounds__(256, 2)
void attn_main(const float* __restrict__ SE, const float* __restrict__ DE,
               const __half* __restrict__ Wh,
               const float* __restrict__ v, const float* __restrict__ bias,
               float* __restrict__ scores) {
    extern __shared__ __align__(128) char smem[];
    const uint32_t sb = smem_u32(smem);
    const int tid = threadIdx.x, wid = tid >> 5, lane = tid & 31;
    const int wm = wid & 3, wn = wid >> 2;
    const int b = blockIdx.y;
    const int s0 = blockIdx.x * 64;

    const float* seb = SE + (size_t)b * Hn * Sn;
    const float* deb = DE + (size_t)b * Hn * Sn;

    // X load mapping: 8 floats/thread: row kr, col chunk c8
    const int kr = tid >> 3;          // 0..31
    const int c8 = (tid & 7) * 8;     // 0..56

    float acc[4][4][4];
#pragma unroll
    for (int mt = 0; mt < 4; mt++)
#pragma unroll
        for (int nt = 0; nt < 4; nt++)
#pragma unroll
            for (int r = 0; r < 4; r++) acc[mt][nt][r] = 0.f;

    // ---- prologue: W stage0 via cp.async, X stage0 via regs ----
    {
        uint32_t s = sb + tid * W_STRIDE;
        const char* gh = (const char*)(Wh + (size_t)tid * 512);
#pragma unroll
        for (int c = 0; c < 4; c++) CP_ASYNC16(s + OFF_WH + c * 16, gh + c * 16);
        CP_COMMIT();
        const float* base = seb + (size_t)kr * Sn + s0 + c8;
        float4 xa = *(const float4*)base;
        float4 xb = *(const float4*)(base + 4);
        uint32_t xoff = (uint32_t)(kr * X_STRIDE + (tid & 7) * 16);
        *(uint4*)(smem + OFF_XH + xoff) = cvt8h(xa, xb);
    }

    const uint32_t arow = (uint32_t)((lane & 15) * W_STRIDE + (lane >> 4) * 16);
    const uint32_t xrow = (uint32_t)((lane & 15) * X_STRIDE + (lane >> 4) * 16);

    float4 xa, xb;
    for (int kc = 0; kc < 16; kc++) {
        const int buf = kc & 1;
        CP_WAIT0();
        __syncthreads();

        if (kc < 15) {
            // prefetch W(kc+1) into buf^1
            uint32_t s = sb + (buf ^ 1) * STAGE + tid * W_STRIDE;
            const char* gh = (const char*)(Wh + (size_t)tid * 512 + (kc + 1) * 32);
#pragma unroll
            for (int c = 0; c < 4; c++) CP_ASYNC16(s + OFF_WH + c * 16, gh + c * 16);
            CP_COMMIT();
            // load X(kc+1) into regs
            int kn = kc + 1;
            const float* base = ((kn < 8) ? seb : deb)
                              + (size_t)((kn & 7) * 32 + kr) * Sn + s0 + c8;
            xa = *(const float4*)base;
            xb = *(const float4*)(base + 4);
        }

        // ---- MMA on stage buf ----
        const uint32_t stage = sb + buf * STAGE;
#pragma unroll
        for (int ks = 0; ks < 2; ks++) {
            uint32_t aH[4][4], bH[4][2];
#pragma unroll
            for (int mt = 0; mt < 4; mt++) {
                uint32_t ad = stage + OFF_WH
                    + (uint32_t)((wm * 64 + mt * 16) * W_STRIDE + ks * 32) + arow;
                ldsm_x4(aH[mt], ad);
            }
#pragma unroll
            for (int np = 0; np < 2; np++) {
                uint32_t bd = stage + OFF_XH
                    + (uint32_t)(ks * 16 * X_STRIDE + (wn * 32 + np * 16) * 2) + xrow;
                uint32_t t[4];
                ldsm_x4_t(t, bd);
                bH[2 * np][0] = t[0];     bH[2 * np][1] = t[1];
                bH[2 * np + 1][0] = t[2]; bH[2 * np + 1][1] = t[3];
            }
#pragma unroll
            for (int mt = 0; mt < 4; mt++)
#pragma unroll
                for (int nt = 0; nt < 4; nt++)
                    mma_f16(acc[mt][nt], aH[mt], bH[nt]);
        }

        if (kc < 15) {
            uint32_t xoff = (uint32_t)((buf ^ 1) * STAGE + kr * X_STRIDE + (tid & 7) * 16);
            *(uint4*)(smem + OFF_XH + xoff) = cvt8h(xa, xb);
        }
    }

    // ---- epilogue: p = v[h]*tanh(acc+bias[h]); reduce over h ----
    float colsum[4][2];
#pragma unroll
    for (int nt = 0; nt < 4; nt++) { colsum[nt][0] = 0.f; colsum[nt][1] = 0.f; }

#pragma unroll
    for (int mt = 0; mt < 4; mt++) {
        int h0 = wm * 64 + mt * 16 + (lane >> 2);
        float bi0 = bias[b * Hn + h0],     v0 = v[h0];
        float bi1 = bias[b * Hn + h0 + 8], v1 = v[h0 + 8];
#pragma unroll
        for (int nt = 0; nt < 4; nt++) {
            colsum[nt][0] += v0 * tanh_acc(acc[mt][nt][0] + bi0)
                           + v1 * tanh_acc(acc[mt][nt][2] + bi1);
            colsum[nt][1] += v0 * tanh_acc(acc[mt][nt][1] + bi0)
                           + v1 * tanh_acc(acc[mt][nt][3] + bi1);
        }
    }
#pragma unroll
    for (int off = 4; off < 32; off <<= 1)
#pragma unroll
        for (int nt = 0; nt < 4; nt++) {
            colsum[nt][0] += __shfl_xor_sync(0xffffffffu, colsum[nt][0], off);
            colsum[nt][1] += __shfl_xor_sync(0xffffffffu, colsum[nt][1], off);
        }

    __syncthreads();  // stage data no longer needed
    float* spart = (float*)smem;  // [4][64]
    if (lane < 4) {
#pragma unroll
        for (int nt = 0; nt < 4; nt++) {
            spart[wm * 64 + wn * 32 + nt * 8 + lane * 2 + 0] = colsum[nt][0];
            spart[wm * 64 + wn * 32 + nt * 8 + lane * 2 + 1] = colsum[nt][1];
        }
    }
    __syncthreads();
    if (tid < 64) {
        float sc = spart[tid] + spart[64 + tid] + spart[128 + tid] + spart[192 + tid];
        scores[(size_t)b * Sn + s0 + tid] = sc;
    }
}

// ---------------------------------------------------------------------------
__global__ void softmax_kernel(const float* __restrict__ scores,
                               float* __restrict__ out) {
    const int b = blockIdx.x, tid = threadIdx.x;
    const float* row = scores + (size_t)b * Sn;
    float vals[16];
    float mx = -1e30f;
#pragma unroll
    for (int i = 0; i < 16; i++) {
        vals[i] = row[tid + i * 256];
        mx = fmaxf(mx, vals[i]);
    }
#pragma unroll
    for (int off = 16; off; off >>= 1)
        mx = fmaxf(mx, __shfl_xor_sync(0xffffffffu, mx, off));
    __shared__ float sred[8];
    if ((tid & 31) == 0) sred[tid >> 5] = mx;
    __syncthreads();
    float bm = sred[0];
#pragma unroll
    for (int w = 1; w < 8; w++) bm = fmaxf(bm, sred[w]);
    __syncthreads();
    float sum = 0.f;
#pragma unroll
    for (int i = 0; i < 16; i++) { vals[i] = __expf(vals[i] - bm); sum += vals[i]; }
#pragma unroll
    for (int off = 16; off; off >>= 1)
        sum += __shfl_xor_sync(0xffffffffu, sum, off);
    if ((tid & 31) == 0) sred[tid >> 5] = sum;
    __syncthreads();
    float tot = 0.f;
#pragma unroll
    for (int w = 0; w < 8; w++) tot += sred[w];
    float inv = 1.0f / tot;
#pragma unroll
    for (int i = 0; i < 16; i++)
        out[(size_t)b * Sn + tid + i * 256] = vals[i] * inv;
}

// ---------------------------------------------------------------------------
extern "C" void kernel_launch(void* const* d_in, const int* in_sizes, int n_in,
                              void* d_out, int out_size) {
    const float* SE = (const float*)d_in[0];
    const float* DE = (const float*)d_in[1];
    const float* dh = (const float*)d_in[2];
    const float* v  = (const float*)d_in[3];
    const float* W  = (const float*)d_in[4];
    float* out = (float*)d_out;

    __half *wh; float *bias, *scores;
    cudaGetSymbolAddress((void**)&wh, g_Wh);
    cudaGetSymbolAddress((void**)&bias, g_bias);
    cudaGetSymbolAddress((void**)&scores, g_scores);

    cudaFuncSetAttribute(attn_main, cudaFuncAttributeMaxDynamicSharedMemorySize, SMEM_SZ);

    convert_w_kernel<<<128, 256>>>(W, wh);
    bias_kernel<<<Bn, 1024>>>(W, dh, bias);
    attn_main<<<dim3(64, Bn), 256, SMEM_SZ>>>(SE, DE, wh, v, bias, scores);
    softmax_kernel<<<Bn, 256>>>(scores, out);
}